// round 15
// baseline (speedup 1.0000x reference)
#include <cuda_runtime.h>
#include <cuda_fp16.h>
#include <cstdint>

// ===================== problem constants =====================
static constexpr int Zb = 4, Hb = 16, Gb = 4, Sq = 4096, NBb = 128, Dd = 128;
static constexpr int TILE_M  = 128;
static constexpr int THREADS = 256;
static constexpr float SM_SCALE = 0.0883883476483184406f; // 1/sqrt(128)

// ===================== pre-converted K/V scratch (fp16) =====================
static constexpr int KV_ELEMS = Zb * Gb * NBb * Dd;   // 262144
__device__ __align__(16) __half g_khi[KV_ELEMS];
__device__ __align__(16) __half g_vhi[KV_ELEMS];

// ===================== smem layout (bytes) =====================
// tiles: 128 rows x 128 fp16 = 32 KB, xor-swizzled in 16B chunks
// P (softmax probs) reuses the K buffer (K dead after GEMM1).
static constexpr int SM_K_HI = 0;
static constexpr int SM_P    = 0;        // alias of K buffer
static constexpr int SM_V_HI = 32768;
static constexpr int SM_TOTAL = 65536;   // 64 KB -> 3 CTAs/SM fit (<=75.6KB each)

// ===================== helpers =====================
__device__ __forceinline__ uint32_t smem_u32(const void* p) {
    uint32_t a;
    asm("{ .reg .u64 t; cvta.to.shared.u64 t, %1; cvt.u32.u64 %0, t; }" : "=r"(a) : "l"(p));
    return a;
}
// byte offset of fp16 element (row, colh) in a swizzled 128x128 fp16 tile
__device__ __forceinline__ uint32_t swz(uint32_t row, uint32_t colh) {
    return row * 256u + ((((colh >> 3) ^ (row & 7u)) << 4) | ((colh & 7u) << 1));
}
__device__ __forceinline__ uint32_t packh(__half a, __half b) {
    __half2 t = __halves2half2(a, b);
    return *reinterpret_cast<uint32_t*>(&t);
}
// scale fp32 pair -> packed fp16x2
__device__ __forceinline__ uint32_t cvt2(float2 f) {
    __half2 t = __floats2half2_rn(f.x * SM_SCALE, f.y * SM_SCALE);
    return *reinterpret_cast<uint32_t*>(&t);
}

#define LDSM4(R, ADDR) \
    asm volatile("ldmatrix.sync.aligned.m8n8.x4.shared.b16 {%0,%1,%2,%3}, [%4];" \
                 : "=r"((R)[0]), "=r"((R)[1]), "=r"((R)[2]), "=r"((R)[3]) : "r"(ADDR))
#define LDSM4T(R, ADDR) \
    asm volatile("ldmatrix.sync.aligned.m8n8.x4.trans.shared.b16 {%0,%1,%2,%3}, [%4];" \
                 : "=r"((R)[0]), "=r"((R)[1]), "=r"((R)[2]), "=r"((R)[3]) : "r"(ADDR))
#define MMA16816(C, A, B0, B1) \
    asm volatile("mma.sync.aligned.m16n8k16.row.col.f32.f16.f16.f32 " \
                 "{%0,%1,%2,%3}, {%4,%5,%6,%7}, {%8,%9}, {%0,%1,%2,%3};" \
                 : "+f"((C)[0]), "+f"((C)[1]), "+f"((C)[2]), "+f"((C)[3]) \
                 : "r"((A)[0]), "r"((A)[1]), "r"((A)[2]), "r"((A)[3]), "r"(B0), "r"(B1))
#define CP16(DST, SRC) \
    asm volatile("cp.async.cg.shared.global [%0], [%1], 16;" :: "r"(DST), "l"(SRC))
#define STS32(ADDR, V) \
    asm volatile("st.shared.b32 [%0], %1;" :: "r"(ADDR), "r"(V) : "memory")

// ===================== kernel 1: convert K/V fp32 -> fp16 =====================
__global__ void presplit_kernel(const float* __restrict__ kb, const float* __restrict__ vb) {
    int i = blockIdx.x * blockDim.x + threadIdx.x;      // float4 index
    const int n4 = KV_ELEMS / 4;
    const float4* src;
    __half* dst;
    if (i < n4) { src = (const float4*)kb; dst = g_khi; }
    else        { i -= n4; src = (const float4*)vb; dst = g_vhi; }
    float4 v = src[i];
    __half h0 = __float2half_rn(v.x), h1 = __float2half_rn(v.y);
    __half h2 = __float2half_rn(v.z), h3 = __float2half_rn(v.w);
    *reinterpret_cast<uint2*>(dst + 4 * i) = make_uint2(packh(h0, h1), packh(h2, h3));
}

// ===================== kernel 2: attention =====================
__global__ void __launch_bounds__(THREADS, 3)
nsa_mma_kernel(const float* __restrict__ q, float* __restrict__ out)
{
    extern __shared__ char smem[];
    const uint32_t sb = smem_u32(smem);
    const int tid  = threadIdx.x;
    const int lane = tid & 31;
    const int w    = tid >> 5;

    const int tile = blockIdx.x;            // 0..31
    const int h    = blockIdx.y;            // 0..15
    const int z    = blockIdx.z;            // 0..3
    const int g    = h >> 2;                // Hb/Gb = 4

    // causal extent: blocks j valid for this tile satisfy j < 4*(tile+1)
    const int KS2 = min(8, (4 * tile + 4 + 15) >> 4);   // k16 steps over block dim
    const int NT  = 2 * KS2;                            // n8 tiles of score matrix
    const int rows_kv = KS2 * 16;

    // ---- K then V via cp.async, separate commit groups (V overlaps GEMM1) ----
    const size_t kvbase = (size_t)(z * Gb + g) * NBb * Dd;
    for (int c = tid; c < rows_kv * 16; c += THREADS) {
        const int row = c >> 4, ch = c & 15;
        const uint32_t dof = row * 256u + (uint32_t)((ch ^ (row & 7)) << 4);
        CP16(sb + SM_K_HI + dof, g_khi + kvbase + (size_t)row * 128 + ch * 8);
    }
    asm volatile("cp.async.commit_group;");
    for (int c = tid; c < rows_kv * 16; c += THREADS) {
        const int row = c >> 4, ch = c & 15;
        const uint32_t dof = row * 256u + (uint32_t)((ch ^ (row & 7)) << 4);
        CP16(sb + SM_V_HI + dof, g_vhi + kvbase + (size_t)row * 128 + ch * 8);
    }
    asm volatile("cp.async.commit_group;");
    asm volatile("cp.async.wait_group 1;" ::: "memory");   // K ready; V in flight
    __syncthreads();

    // ===================== GEMM1: S = Q K^T (single pass: Qhi * Khi) =====================
    float acc[16][4];
    #pragma unroll
    for (int i = 0; i < 16; i++) { acc[i][0] = acc[i][1] = acc[i][2] = acc[i][3] = 0.f; }

    const int m0 = w * 16;
    const int rA = m0 + (lane >> 2);
    const int q4 = (lane & 3) * 2;
    const float* qlane = q + (((size_t)z * Hb + h) * Sq + (size_t)tile * TILE_M + rA) * Dd + q4;

    const uint32_t brow8 = (uint32_t)(((lane >> 4) << 3) + (lane & 7));
    const uint32_t bcolx = (uint32_t)(((lane >> 3) & 1) << 3);

    #pragma unroll
    for (int ks = 0; ks < 8; ks++) {
        float2 f0 = *reinterpret_cast<const float2*>(qlane + ks * 16);
        float2 f1 = *reinterpret_cast<const float2*>(qlane + 8 * Dd + ks * 16);
        float2 f2 = *reinterpret_cast<const float2*>(qlane + ks * 16 + 8);
        float2 f3 = *reinterpret_cast<const float2*>(qlane + 8 * Dd + ks * 16 + 8);
        uint32_t aH[4];
        aH[0] = cvt2(f0);
        aH[1] = cvt2(f1);
        aH[2] = cvt2(f2);
        aH[3] = cvt2(f3);
        #pragma unroll
        for (int np = 0; np < 8; np++) {
            if (np < KS2) {
                uint32_t bH[4];
                LDSM4(bH, sb + SM_K_HI + swz(np * 16 + brow8, ks * 16 + bcolx));
                MMA16816(acc[2 * np],     aH, bH[0], bH[1]);
                MMA16816(acc[2 * np + 1], aH, bH[2], bH[3]);
            }
        }
    }

    // All warps done reading K before P overwrites the K buffer
    __syncthreads();

    // ===================== softmax (in-register, mask by formula) =====================
    // block_ends[j] = 32(j+1)-1  =>  valid iff j < (m+1)>>5
    const int mA = tile * TILE_M + rA;
    const int limA = (mA + 1) >> 5;
    const int limB = (mA + 9) >> 5;          // row mA+8

    float mxA = -1e30f, mxB = -1e30f;
    #pragma unroll
    for (int nt = 0; nt < 16; nt++) if (nt < NT) {
        const int j0 = nt * 8 + q4, j1 = j0 + 1;
        if (j0 < limA) mxA = fmaxf(mxA, acc[nt][0]);
        if (j1 < limA) mxA = fmaxf(mxA, acc[nt][1]);
        if (j0 < limB) mxB = fmaxf(mxB, acc[nt][2]);
        if (j1 < limB) mxB = fmaxf(mxB, acc[nt][3]);
    }
    mxA = fmaxf(mxA, __shfl_xor_sync(0xffffffffu, mxA, 1));
    mxA = fmaxf(mxA, __shfl_xor_sync(0xffffffffu, mxA, 2));
    mxB = fmaxf(mxB, __shfl_xor_sync(0xffffffffu, mxB, 1));
    mxB = fmaxf(mxB, __shfl_xor_sync(0xffffffffu, mxB, 2));

    // P -> SMEM (fp16, same swizzled layout; rows = queries, cols = blocks)
    float lA = 0.f, lB = 0.f;
    #pragma unroll
    for (int nt = 0; nt < 16; nt++) if (nt < NT) {
        const int j0 = nt * 8 + q4, j1 = j0 + 1;
        const float p0A = (j0 < limA) ? __expf(acc[nt][0] - mxA) : 0.f;
        const float p1A = (j1 < limA) ? __expf(acc[nt][1] - mxA) : 0.f;
        const float p0B = (j0 < limB) ? __expf(acc[nt][2] - mxB) : 0.f;
        const float p1B = (j1 < limB) ? __expf(acc[nt][3] - mxB) : 0.f;
        lA += p0A + p1A;
        lB += p0B + p1B;
        const uint32_t uA = packh(__float2half_rn(p0A), __float2half_rn(p1A));
        const uint32_t uB = packh(__float2half_rn(p0B), __float2half_rn(p1B));
        STS32(sb + SM_P + swz((uint32_t)rA,       (uint32_t)j0), uA);
        STS32(sb + SM_P + swz((uint32_t)(rA + 8), (uint32_t)j0), uB);
    }
    lA += __shfl_xor_sync(0xffffffffu, lA, 1);
    lA += __shfl_xor_sync(0xffffffffu, lA, 2);
    lB += __shfl_xor_sync(0xffffffffu, lB, 1);
    lB += __shfl_xor_sync(0xffffffffu, lB, 2);

    // V resident + P visible before GEMM2 LDSMs
    asm volatile("cp.async.wait_group 0;" ::: "memory");
    __syncthreads();

    // ===================== GEMM2: O = P V (A from SMEM via ldmatrix) =====================
    float oacc[16][4];
    #pragma unroll
    for (int i = 0; i < 16; i++) { oacc[i][0] = oacc[i][1] = oacc[i][2] = oacc[i][3] = 0.f; }

    const uint32_t arow  = (uint32_t)(m0 + (lane & 15));
    const uint32_t acolx = (uint32_t)((lane >> 4) << 3);
    const uint32_t vrow8 = (uint32_t)((((lane >> 3) & 1) << 3) + (lane & 7));
    const uint32_t vcolx = (uint32_t)((lane >> 4) << 3);

    #pragma unroll
    for (int ks2 = 0; ks2 < 8; ks2++) if (ks2 < KS2) {
        uint32_t aP[4];
        LDSM4(aP, sb + SM_P + swz(arow, ks2 * 16 + acolx));
        #pragma unroll
        for (int np = 0; np < 8; np++) {
            const uint32_t voff = swz(ks2 * 16 + vrow8, np * 16 + vcolx);
            uint32_t bH[4];
            LDSM4T(bH, sb + SM_V_HI + voff);
            MMA16816(oacc[2 * np],     aP, bH[0], bH[1]);
            MMA16816(oacc[2 * np + 1], aP, bH[2], bH[3]);
        }
    }

    // ===================== epilogue: normalize + store =====================
    const float invA = (lA > 0.f) ? (1.f / lA) : 0.f;
    const float invB = (lB > 0.f) ? (1.f / lB) : 0.f;
    float* op = out + (((size_t)z * Hb + h) * Sq + (size_t)tile * TILE_M + rA) * Dd;
    #pragma unroll
    for (int nt = 0; nt < 16; nt++) {
        const int dv0 = nt * 8 + q4;
        *reinterpret_cast<float2*>(op + dv0) =
            make_float2(oacc[nt][0] * invA, oacc[nt][1] * invA);
        *reinterpret_cast<float2*>(op + (size_t)8 * Dd + dv0) =
            make_float2(oacc[nt][2] * invB, oacc[nt][3] * invB);
    }
}

// ===================== launch =====================
extern "C" void kernel_launch(void* const* d_in, const int* in_sizes, int n_in,
                              void* d_out, int out_size) {
    const float* q  = (const float*)d_in[0];
    const float* kb = (const float*)d_in[1];
    const float* vb = (const float*)d_in[2];
    float* out = (float*)d_out;

    presplit_kernel<<<(2 * (KV_ELEMS / 4)) / 256, 256>>>(kb, vb);

    cudaFuncSetAttribute(nsa_mma_kernel,
                         cudaFuncAttributeMaxDynamicSharedMemorySize, SM_TOTAL);
    dim3 grid(Sq / TILE_M, Hb, Zb);   // (32, 16, 4)
    nsa_mma_kernel<<<grid, THREADS, SM_TOTAL>>>(q, out);
}

// round 16
// speedup vs baseline: 1.3226x; 1.3226x over previous
#include <cuda_runtime.h>
#include <cuda_fp16.h>
#include <cstdint>

// ===================== problem constants =====================
static constexpr int Zb = 4, Hb = 16, Gb = 4, Sq = 4096, NBb = 128, Dd = 128;
static constexpr int TILE_M  = 128;
static constexpr int THREADS = 256;
static constexpr float SM_SCALE = 0.0883883476483184406f; // 1/sqrt(128)

// ===================== pre-converted K/V scratch (fp16, k/n-permuted) =====================
// Within every 16-col group, smem/global col m holds real col pi(m):
// pi = {0,1,4,5, 8,9,12,13, 2,3,6,7, 10,11,14,15}
// This makes lane qi's MMA fragment slots {2qi,2qi+1,2qi+8,2qi+9} correspond to
// real cols {4qi..4qi+3}, enabling float4 Q loads / O stores with no shuffles.
static constexpr int KV_ELEMS = Zb * Gb * NBb * Dd;   // 262144
__device__ __align__(16) __half g_khi[KV_ELEMS];
__device__ __align__(16) __half g_vhi[KV_ELEMS];

// ===================== smem layout (bytes) =====================
// tiles: 128 rows x 128 fp16 = 32 KB, xor-swizzled in 16B chunks
static constexpr int SM_K_HI = 0;
static constexpr int SM_V_HI = 32768;
static constexpr int SM_TOTAL = 65536;

// ===================== helpers =====================
__device__ __forceinline__ uint32_t smem_u32(const void* p) {
    uint32_t a;
    asm("{ .reg .u64 t; cvta.to.shared.u64 t, %1; cvt.u32.u64 %0, t; }" : "=r"(a) : "l"(p));
    return a;
}
// byte offset of fp16 element (row, colh) in a swizzled 128x128 fp16 tile
__device__ __forceinline__ uint32_t swz(uint32_t row, uint32_t colh) {
    return row * 256u + ((((colh >> 3) ^ (row & 7u)) << 4) | ((colh & 7u) << 1));
}
__device__ __forceinline__ uint32_t packh(__half a, __half b) {
    __half2 t = __halves2half2(a, b);
    return *reinterpret_cast<uint32_t*>(&t);
}
// scale fp32 pair -> packed fp16x2
__device__ __forceinline__ uint32_t cvt2(float x, float y) {
    __half2 t = __floats2half2_rn(x * SM_SCALE, y * SM_SCALE);
    return *reinterpret_cast<uint32_t*>(&t);
}

#define LDSM4(R, ADDR) \
    asm volatile("ldmatrix.sync.aligned.m8n8.x4.shared.b16 {%0,%1,%2,%3}, [%4];" \
                 : "=r"((R)[0]), "=r"((R)[1]), "=r"((R)[2]), "=r"((R)[3]) : "r"(ADDR))
#define LDSM4T(R, ADDR) \
    asm volatile("ldmatrix.sync.aligned.m8n8.x4.trans.shared.b16 {%0,%1,%2,%3}, [%4];" \
                 : "=r"((R)[0]), "=r"((R)[1]), "=r"((R)[2]), "=r"((R)[3]) : "r"(ADDR))
#define MMA16816(C, A, B0, B1) \
    asm volatile("mma.sync.aligned.m16n8k16.row.col.f32.f16.f16.f32 " \
                 "{%0,%1,%2,%3}, {%4,%5,%6,%7}, {%8,%9}, {%0,%1,%2,%3};" \
                 : "+f"((C)[0]), "+f"((C)[1]), "+f"((C)[2]), "+f"((C)[3]) \
                 : "r"((A)[0]), "r"((A)[1]), "r"((A)[2]), "r"((A)[3]), "r"(B0), "r"(B1))
#define CP16(DST, SRC) \
    asm volatile("cp.async.cg.shared.global [%0], [%1], 16;" :: "r"(DST), "l"(SRC))

// ===================== kernel 1: convert + permute K/V fp32 -> fp16 =====================
// dst cols [4s..4s+3] of each 16-col group take real cols (p,p+1,p+4,p+5),
// p = ((s&1)<<3) | (s&2):  s=0->0, s=1->8, s=2->2, s=3->10.
__global__ void presplit_kernel(const float* __restrict__ kb, const float* __restrict__ vb) {
    int i = blockIdx.x * blockDim.x + threadIdx.x;      // dst half4 index
    const int n4 = KV_ELEMS / 4;
    const float* src;
    __half* dst;
    int e = i;
    if (e < n4) { src = kb; dst = g_khi; }
    else        { e -= n4; src = vb; dst = g_vhi; }
    const int flat = 4 * e;
    const int c = flat & 127;                  // col within row
    const int gbase = (flat - c) + (c & ~15);  // flat index of 16-col group start
    const int s = (c >> 2) & 3;
    const int p = ((s & 1) << 3) | (s & 2);
    float2 u = *reinterpret_cast<const float2*>(src + gbase + p);
    float2 v = *reinterpret_cast<const float2*>(src + gbase + p + 4);
    *reinterpret_cast<uint2*>(dst + flat) =
        make_uint2(packh(__float2half_rn(u.x), __float2half_rn(u.y)),
                   packh(__float2half_rn(v.x), __float2half_rn(v.y)));
}

// ===================== kernel 2: attention =====================
__global__ void __launch_bounds__(THREADS, 2)
nsa_mma_kernel(const float* __restrict__ q, float* __restrict__ out)
{
    extern __shared__ char smem[];
    const uint32_t sb = smem_u32(smem);
    const int tid  = threadIdx.x;
    const int lane = tid & 31;
    const int w    = tid >> 5;

    const int tile = blockIdx.x;            // 0..31
    const int h    = blockIdx.y;            // 0..15
    const int z    = blockIdx.z;            // 0..3
    const int g    = h >> 2;                // Hb/Gb = 4

    // causal extent: blocks j valid for this tile satisfy j < 4*(tile+1)
    const int KS2 = min(8, (4 * tile + 4 + 15) >> 4);   // k16 steps over block dim
    const int NT  = 2 * KS2;                            // n8 tiles of score matrix
    const int rows_kv = KS2 * 16;

    // ---- K then V via cp.async, separate commit groups (V overlaps GEMM1) ----
    const size_t kvbase = (size_t)(z * Gb + g) * NBb * Dd;
    for (int c = tid; c < rows_kv * 16; c += THREADS) {
        const int row = c >> 4, ch = c & 15;
        const uint32_t dof = row * 256u + (uint32_t)((ch ^ (row & 7)) << 4);
        CP16(sb + SM_K_HI + dof, g_khi + kvbase + (size_t)row * 128 + ch * 8);
    }
    asm volatile("cp.async.commit_group;");
    for (int c = tid; c < rows_kv * 16; c += THREADS) {
        const int row = c >> 4, ch = c & 15;
        const uint32_t dof = row * 256u + (uint32_t)((ch ^ (row & 7)) << 4);
        CP16(sb + SM_V_HI + dof, g_vhi + kvbase + (size_t)row * 128 + ch * 8);
    }
    asm volatile("cp.async.commit_group;");
    asm volatile("cp.async.wait_group 1;" ::: "memory");   // K ready; V in flight
    __syncthreads();

    // ===================== GEMM1: S = Q K^T (single pass: Qhi * Khi_perm) =====================
    float acc[16][4];
    #pragma unroll
    for (int i = 0; i < 16; i++) { acc[i][0] = acc[i][1] = acc[i][2] = acc[i][3] = 0.f; }

    const int m0 = w * 16;
    const int rA = m0 + (lane >> 2);
    const int q4 = (lane & 3) * 2;   // fragment n-position (blocks) — unpermuted
    const int qc = (lane & 3) * 4;   // real-column base for float4 Q load / O store
    const float* qlane = q + (((size_t)z * Hb + h) * Sq + (size_t)tile * TILE_M + rA) * Dd + qc;

    const uint32_t brow8 = (uint32_t)(((lane >> 4) << 3) + (lane & 7));
    const uint32_t bcolx = (uint32_t)(((lane >> 3) & 1) << 3);

    #pragma unroll
    for (int ks = 0; ks < 8; ks++) {
        float4 fr0 = *reinterpret_cast<const float4*>(qlane + ks * 16);
        float4 fr1 = *reinterpret_cast<const float4*>(qlane + 8 * Dd + ks * 16);
        uint32_t aH[4];
        aH[0] = cvt2(fr0.x, fr0.y);   // k-slots 2qi,2qi+1  = real cols 4qi,4qi+1
        aH[1] = cvt2(fr1.x, fr1.y);
        aH[2] = cvt2(fr0.z, fr0.w);   // k-slots 2qi+8,+9   = real cols 4qi+2,4qi+3
        aH[3] = cvt2(fr1.z, fr1.w);
        #pragma unroll
        for (int np = 0; np < 8; np++) {
            if (np < KS2) {
                uint32_t bH[4];
                LDSM4(bH, sb + SM_K_HI + swz(np * 16 + brow8, ks * 16 + bcolx));
                MMA16816(acc[2 * np],     aH, bH[0], bH[1]);
                MMA16816(acc[2 * np + 1], aH, bH[2], bH[3]);
            }
        }
    }

    // ===================== softmax (in-register, mask by formula) =====================
    // block_ends[j] = 32(j+1)-1  =>  valid iff j < (m+1)>>5
    const int mA = tile * TILE_M + rA;
    const int limA = (mA + 1) >> 5;
    const int limB = (mA + 9) >> 5;          // row mA+8

    float mxA = -1e30f, mxB = -1e30f;
    #pragma unroll
    for (int nt = 0; nt < 16; nt++) if (nt < NT) {
        const int j0 = nt * 8 + q4, j1 = j0 + 1;
        if (j0 < limA) mxA = fmaxf(mxA, acc[nt][0]);
        if (j1 < limA) mxA = fmaxf(mxA, acc[nt][1]);
        if (j0 < limB) mxB = fmaxf(mxB, acc[nt][2]);
        if (j1 < limB) mxB = fmaxf(mxB, acc[nt][3]);
    }
    mxA = fmaxf(mxA, __shfl_xor_sync(0xffffffffu, mxA, 1));
    mxA = fmaxf(mxA, __shfl_xor_sync(0xffffffffu, mxA, 2));
    mxB = fmaxf(mxB, __shfl_xor_sync(0xffffffffu, mxB, 1));
    mxB = fmaxf(mxB, __shfl_xor_sync(0xffffffffu, mxB, 2));

    float lA = 0.f, lB = 0.f;
    uint32_t pA[8][4];   // A-fragments of P for GEMM2 (k = blocks, unpermuted)
    #pragma unroll
    for (int nt = 0; nt < 16; nt++) if (nt < NT) {
        const int j0 = nt * 8 + q4, j1 = j0 + 1;
        const float p0A = (j0 < limA) ? __expf(acc[nt][0] - mxA) : 0.f;
        const float p1A = (j1 < limA) ? __expf(acc[nt][1] - mxA) : 0.f;
        const float p0B = (j0 < limB) ? __expf(acc[nt][2] - mxB) : 0.f;
        const float p1B = (j1 < limB) ? __expf(acc[nt][3] - mxB) : 0.f;
        lA += p0A + p1A;
        lB += p0B + p1B;
        const uint32_t uA = packh(__float2half_rn(p0A), __float2half_rn(p1A));
        const uint32_t uB = packh(__float2half_rn(p0B), __float2half_rn(p1B));
        pA[nt >> 1][(nt & 1) ? 2 : 0] = uA;
        pA[nt >> 1][(nt & 1) ? 3 : 1] = uB;
    }
    lA += __shfl_xor_sync(0xffffffffu, lA, 1);
    lA += __shfl_xor_sync(0xffffffffu, lA, 2);
    lB += __shfl_xor_sync(0xffffffffu, lB, 1);
    lB += __shfl_xor_sync(0xffffffffu, lB, 2);

    // V must be resident before GEMM2 LDSMs
    asm volatile("cp.async.wait_group 0;" ::: "memory");
    __syncthreads();

    // ===================== GEMM2: O = P V (single pass, V hi, dv permuted) =====================
    float oacc[16][4];
    #pragma unroll
    for (int i = 0; i < 16; i++) { oacc[i][0] = oacc[i][1] = oacc[i][2] = oacc[i][3] = 0.f; }

    const uint32_t vrow8 = (uint32_t)((((lane >> 3) & 1) << 3) + (lane & 7));
    const uint32_t vcolx = (uint32_t)((lane >> 4) << 3);

    #pragma unroll
    for (int ks2 = 0; ks2 < 8; ks2++) if (ks2 < KS2) {
        #pragma unroll
        for (int np = 0; np < 8; np++) {
            const uint32_t voff = swz(ks2 * 16 + vrow8, np * 16 + vcolx);
            uint32_t bH[4];
            LDSM4T(bH, sb + SM_V_HI + voff);
            MMA16816(oacc[2 * np],     pA[ks2], bH[0], bH[1]);
            MMA16816(oacc[2 * np + 1], pA[ks2], bH[2], bH[3]);
        }
    }

    // ===================== epilogue: normalize + float4 stores =====================
    // lane qi's fragment n-slots of (oacc[2np], oacc[2np+1]) = real dv {4qi..4qi+3}
    const float invA = (lA > 0.f) ? (1.f / lA) : 0.f;
    const float invB = (lB > 0.f) ? (1.f / lB) : 0.f;
    float* op = out + (((size_t)z * Hb + h) * Sq + (size_t)tile * TILE_M + rA) * Dd + qc;
    #pragma unroll
    for (int np = 0; np < 8; np++) {
        *reinterpret_cast<float4*>(op + np * 16) =
            make_float4(oacc[2 * np][0] * invA, oacc[2 * np][1] * invA,
                        oacc[2 * np + 1][0] * invA, oacc[2 * np + 1][1] * invA);
        *reinterpret_cast<float4*>(op + (size_t)8 * Dd + np * 16) =
            make_float4(oacc[2 * np][2] * invB, oacc[2 * np][3] * invB,
                        oacc[2 * np + 1][2] * invB, oacc[2 * np + 1][3] * invB);
    }
}

// ===================== launch =====================
extern "C" void kernel_launch(void* const* d_in, const int* in_sizes, int n_in,
                              void* d_out, int out_size) {
    const float* q  = (const float*)d_in[0];
    const float* kb = (const float*)d_in[1];
    const float* vb = (const float*)d_in[2];
    float* out = (float*)d_out;

    presplit_kernel<<<(2 * (KV_ELEMS / 4)) / 256, 256>>>(kb, vb);

    cudaFuncSetAttribute(nsa_mma_kernel,
                         cudaFuncAttributeMaxDynamicSharedMemorySize, SM_TOTAL);
    dim3 grid(Sq / TILE_M, Hb, Zb);   // (32, 16, 4)
    nsa_mma_kernel<<<grid, THREADS, SM_TOTAL>>>(q, out);
}

// round 17
// speedup vs baseline: 1.3837x; 1.0462x over previous
#include <cuda_runtime.h>
#include <cuda_fp16.h>
#include <cstdint>

// ===================== problem constants =====================
static constexpr int Zb = 4, Hb = 16, Gb = 4, Sq = 4096, NBb = 128, Dd = 128;
static constexpr int TILE_M  = 128;
static constexpr int THREADS = 256;
static constexpr float SM_SCALE = 0.0883883476483184406f; // 1/sqrt(128)

// ===================== pre-converted K/V scratch (fp16, k/n-permuted) =====================
// Within every 16-col group, stored col m holds real col pi(m):
// pi = {0,1,4,5, 8,9,12,13, 2,3,6,7, 10,11,14,15}
// K additionally pre-scaled by SM_SCALE (folded out of the Q convert path).
static constexpr int KV_ELEMS = Zb * Gb * NBb * Dd;   // 262144
__device__ __align__(16) __half g_khi[KV_ELEMS];
__device__ __align__(16) __half g_vhi[KV_ELEMS];

// ===================== smem layout (bytes) =====================
static constexpr int SM_K_HI = 0;
static constexpr int SM_V_HI = 32768;
static constexpr int SM_TOTAL = 65536;

// ===================== helpers =====================
__device__ __forceinline__ uint32_t smem_u32(const void* p) {
    uint32_t a;
    asm("{ .reg .u64 t; cvta.to.shared.u64 t, %1; cvt.u32.u64 %0, t; }" : "=r"(a) : "l"(p));
    return a;
}
__device__ __forceinline__ uint32_t swz(uint32_t row, uint32_t colh) {
    return row * 256u + ((((colh >> 3) ^ (row & 7u)) << 4) | ((colh & 7u) << 1));
}
__device__ __forceinline__ uint32_t packh(__half a, __half b) {
    __half2 t = __halves2half2(a, b);
    return *reinterpret_cast<uint32_t*>(&t);
}
__device__ __forceinline__ uint32_t cvt2(float x, float y) {   // no scale (folded into K)
    __half2 t = __floats2half2_rn(x, y);
    return *reinterpret_cast<uint32_t*>(&t);
}

#define LDSM4(R, ADDR) \
    asm volatile("ldmatrix.sync.aligned.m8n8.x4.shared.b16 {%0,%1,%2,%3}, [%4];" \
                 : "=r"((R)[0]), "=r"((R)[1]), "=r"((R)[2]), "=r"((R)[3]) : "r"(ADDR))
#define LDSM4T(R, ADDR) \
    asm volatile("ldmatrix.sync.aligned.m8n8.x4.trans.shared.b16 {%0,%1,%2,%3}, [%4];" \
                 : "=r"((R)[0]), "=r"((R)[1]), "=r"((R)[2]), "=r"((R)[3]) : "r"(ADDR))
#define MMA16816(C, A, B0, B1) \
    asm volatile("mma.sync.aligned.m16n8k16.row.col.f32.f16.f16.f32 " \
                 "{%0,%1,%2,%3}, {%4,%5,%6,%7}, {%8,%9}, {%0,%1,%2,%3};" \
                 : "+f"((C)[0]), "+f"((C)[1]), "+f"((C)[2]), "+f"((C)[3]) \
                 : "r"((A)[0]), "r"((A)[1]), "r"((A)[2]), "r"((A)[3]), "r"(B0), "r"(B1))
#define CP16(DST, SRC) \
    asm volatile("cp.async.cg.shared.global [%0], [%1], 16;" :: "r"(DST), "l"(SRC))

// ===================== kernel 1: convert + permute K/V fp32 -> fp16 =====================
// dst cols [4s..4s+3] of each 16-col group take real cols (p,p+1,p+4,p+5),
// p = ((s&1)<<3) | (s&2).  K gets SM_SCALE folded in.
__global__ void presplit_kernel(const float* __restrict__ kb, const float* __restrict__ vb) {
    int i = blockIdx.x * blockDim.x + threadIdx.x;      // dst half4 index
    const int n4 = KV_ELEMS / 4;
    const float* src;
    __half* dst;
    float sc;
    int e = i;
    if (e < n4) { src = kb; dst = g_khi; sc = SM_SCALE; }
    else        { e -= n4; src = vb; dst = g_vhi; sc = 1.0f; }
    const int flat = 4 * e;
    const int c = flat & 127;                  // col within row
    const int gbase = (flat - c) + (c & ~15);  // flat index of 16-col group start
    const int s = (c >> 2) & 3;
    const int p = ((s & 1) << 3) | (s & 2);
    float2 u = *reinterpret_cast<const float2*>(src + gbase + p);
    float2 v = *reinterpret_cast<const float2*>(src + gbase + p + 4);
    *reinterpret_cast<uint2*>(dst + flat) =
        make_uint2(packh(__float2half_rn(u.x * sc), __float2half_rn(u.y * sc)),
                   packh(__float2half_rn(v.x * sc), __float2half_rn(v.y * sc)));
}

// ===================== templated attention body (KS2 compile-time) =====================
template <int KS2>
__device__ __forceinline__ void attn_body(
    uint32_t sb, const float* __restrict__ qlane, float* __restrict__ op,
    int lane, int mA)
{
    constexpr int NT = 2 * KS2;

    // ---------- GEMM1: S = Q K^T ----------
    float acc[NT][4];
    #pragma unroll
    for (int i = 0; i < NT; i++) { acc[i][0] = acc[i][1] = acc[i][2] = acc[i][3] = 0.f; }

    const int q4 = (lane & 3) * 2;   // fragment n-position (blocks)
    const uint32_t brow8 = (uint32_t)(((lane >> 4) << 3) + (lane & 7));
    const uint32_t bcolx = (uint32_t)(((lane >> 3) & 1) << 3);

    #pragma unroll
    for (int ks = 0; ks < 8; ks++) {
        float4 fr0 = *reinterpret_cast<const float4*>(qlane + ks * 16);
        float4 fr1 = *reinterpret_cast<const float4*>(qlane + 8 * Dd + ks * 16);
        uint32_t aH[4];
        aH[0] = cvt2(fr0.x, fr0.y);
        aH[1] = cvt2(fr1.x, fr1.y);
        aH[2] = cvt2(fr0.z, fr0.w);
        aH[3] = cvt2(fr1.z, fr1.w);
        #pragma unroll
        for (int np = 0; np < KS2; np++) {
            uint32_t bH[4];
            LDSM4(bH, sb + SM_K_HI + swz(np * 16 + brow8, ks * 16 + bcolx));
            MMA16816(acc[2 * np],     aH, bH[0], bH[1]);
            MMA16816(acc[2 * np + 1], aH, bH[2], bH[3]);
        }
    }

    // ---------- softmax (mask: valid iff j < (m+1)>>5) ----------
    const int limA = (mA + 1) >> 5;
    const int limB = (mA + 9) >> 5;          // row mA+8

    float mxA = -1e30f, mxB = -1e30f;
    #pragma unroll
    for (int nt = 0; nt < NT; nt++) {
        const int j0 = nt * 8 + q4, j1 = j0 + 1;
        if (j0 < limA) mxA = fmaxf(mxA, acc[nt][0]);
        if (j1 < limA) mxA = fmaxf(mxA, acc[nt][1]);
        if (j0 < limB) mxB = fmaxf(mxB, acc[nt][2]);
        if (j1 < limB) mxB = fmaxf(mxB, acc[nt][3]);
    }
    mxA = fmaxf(mxA, __shfl_xor_sync(0xffffffffu, mxA, 1));
    mxA = fmaxf(mxA, __shfl_xor_sync(0xffffffffu, mxA, 2));
    mxB = fmaxf(mxB, __shfl_xor_sync(0xffffffffu, mxB, 1));
    mxB = fmaxf(mxB, __shfl_xor_sync(0xffffffffu, mxB, 2));

    float lA = 0.f, lB = 0.f;
    uint32_t pA[KS2][4];   // A-fragments of P for GEMM2
    #pragma unroll
    for (int nt = 0; nt < NT; nt++) {
        const int j0 = nt * 8 + q4, j1 = j0 + 1;
        const float p0A = (j0 < limA) ? __expf(acc[nt][0] - mxA) : 0.f;
        const float p1A = (j1 < limA) ? __expf(acc[nt][1] - mxA) : 0.f;
        const float p0B = (j0 < limB) ? __expf(acc[nt][2] - mxB) : 0.f;
        const float p1B = (j1 < limB) ? __expf(acc[nt][3] - mxB) : 0.f;
        lA += p0A + p1A;
        lB += p0B + p1B;
        const uint32_t uA = packh(__float2half_rn(p0A), __float2half_rn(p1A));
        const uint32_t uB = packh(__float2half_rn(p0B), __float2half_rn(p1B));
        pA[nt >> 1][(nt & 1) ? 2 : 0] = uA;
        pA[nt >> 1][(nt & 1) ? 3 : 1] = uB;
    }
    lA += __shfl_xor_sync(0xffffffffu, lA, 1);
    lA += __shfl_xor_sync(0xffffffffu, lA, 2);
    lB += __shfl_xor_sync(0xffffffffu, lB, 1);
    lB += __shfl_xor_sync(0xffffffffu, lB, 2);

    // V must be resident before GEMM2 LDSMs
    asm volatile("cp.async.wait_group 0;" ::: "memory");
    __syncthreads();

    // ---------- GEMM2: O = P V ----------
    float oacc[16][4];
    #pragma unroll
    for (int i = 0; i < 16; i++) { oacc[i][0] = oacc[i][1] = oacc[i][2] = oacc[i][3] = 0.f; }

    const uint32_t vrow8 = (uint32_t)((((lane >> 3) & 1) << 3) + (lane & 7));
    const uint32_t vcolx = (uint32_t)((lane >> 4) << 3);

    #pragma unroll
    for (int ks2 = 0; ks2 < KS2; ks2++) {
        #pragma unroll
        for (int np = 0; np < 8; np++) {
            uint32_t bH[4];
            LDSM4T(bH, sb + SM_V_HI + swz(ks2 * 16 + vrow8, np * 16 + vcolx));
            MMA16816(oacc[2 * np],     pA[ks2], bH[0], bH[1]);
            MMA16816(oacc[2 * np + 1], pA[ks2], bH[2], bH[3]);
        }
    }

    // ---------- epilogue: normalize + float4 stores (dv permuted) ----------
    const float invA = (lA > 0.f) ? (1.f / lA) : 0.f;
    const float invB = (lB > 0.f) ? (1.f / lB) : 0.f;
    #pragma unroll
    for (int np = 0; np < 8; np++) {
        *reinterpret_cast<float4*>(op + np * 16) =
            make_float4(oacc[2 * np][0] * invA, oacc[2 * np][1] * invA,
                        oacc[2 * np + 1][0] * invA, oacc[2 * np + 1][1] * invA);
        *reinterpret_cast<float4*>(op + (size_t)8 * Dd + np * 16) =
            make_float4(oacc[2 * np][2] * invB, oacc[2 * np][3] * invB,
                        oacc[2 * np + 1][2] * invB, oacc[2 * np + 1][3] * invB);
    }
}

// ===================== kernel 2: attention =====================
__global__ void __launch_bounds__(THREADS, 2)
nsa_mma_kernel(const float* __restrict__ q, float* __restrict__ out)
{
    extern __shared__ char smem[];
    const uint32_t sb = smem_u32(smem);
    const int tid  = threadIdx.x;
    const int lane = tid & 31;
    const int w    = tid >> 5;

    const int tile = blockIdx.x;            // 0..31
    const int h    = blockIdx.y;            // 0..15
    const int z    = blockIdx.z;            // 0..3
    const int g    = h >> 2;                // Hb/Gb = 4

    const int KS2 = (tile >> 2) + 1;        // 1..8 (= ceil((4*tile+4)/16))
    const int rows_kv = KS2 * 16;

    // ---- K then V via cp.async, separate commit groups (V overlaps GEMM1) ----
    const size_t kvbase = (size_t)(z * Gb + g) * NBb * Dd;
    for (int c = tid; c < rows_kv * 16; c += THREADS) {
        const int row = c >> 4, ch = c & 15;
        const uint32_t dof = row * 256u + (uint32_t)((ch ^ (row & 7)) << 4);
        CP16(sb + SM_K_HI + dof, g_khi + kvbase + (size_t)row * 128 + ch * 8);
    }
    asm volatile("cp.async.commit_group;");
    for (int c = tid; c < rows_kv * 16; c += THREADS) {
        const int row = c >> 4, ch = c & 15;
        const uint32_t dof = row * 256u + (uint32_t)((ch ^ (row & 7)) << 4);
        CP16(sb + SM_V_HI + dof, g_vhi + kvbase + (size_t)row * 128 + ch * 8);
    }
    asm volatile("cp.async.commit_group;");
    asm volatile("cp.async.wait_group 1;" ::: "memory");   // K ready; V in flight
    __syncthreads();

    const int rA = w * 16 + (lane >> 2);
    const int qc = (lane & 3) * 4;          // real-column base (permuted layout)
    const int mA = tile * TILE_M + rA;
    const float* qlane = q + (((size_t)z * Hb + h) * Sq + (size_t)tile * TILE_M + rA) * Dd + qc;
    float* op = out + (((size_t)z * Hb + h) * Sq + (size_t)tile * TILE_M + rA) * Dd + qc;

    switch (tile >> 2) {
        case 0: attn_body<1>(sb, qlane, op, lane, mA); break;
        case 1: attn_body<2>(sb, qlane, op, lane, mA); break;
        case 2: attn_body<3>(sb, qlane, op, lane, mA); break;
        case 3: attn_body<4>(sb, qlane, op, lane, mA); break;
        case 4: attn_body<5>(sb, qlane, op, lane, mA); break;
        case 5: attn_body<6>(sb, qlane, op, lane, mA); break;
        case 6: attn_body<7>(sb, qlane, op, lane, mA); break;
        default: attn_body<8>(sb, qlane, op, lane, mA); break;
    }
}

// ===================== launch =====================
extern "C" void kernel_launch(void* const* d_in, const int* in_sizes, int n_in,
                              void* d_out, int out_size) {
    const float* q  = (const float*)d_in[0];
    const float* kb = (const float*)d_in[1];
    const float* vb = (const float*)d_in[2];
    float* out = (float*)d_out;

    presplit_kernel<<<(2 * (KV_ELEMS / 4)) / 256, 256>>>(kb, vb);

    cudaFuncSetAttribute(nsa_mma_kernel,
                         cudaFuncAttributeMaxDynamicSharedMemorySize, SM_TOTAL);
    dim3 grid(Sq / TILE_M, Hb, Zb);   // (32, 16, 4)
    nsa_mma_kernel<<<grid, THREADS, SM_TOTAL>>>(q, out);
}